// round 6
// baseline (speedup 1.0000x reference)
#include <cuda_runtime.h>
#include <cstdint>
#include <cstddef>

// Problem constants
#define Bsz 128
#define Tn  1024
#define Dn  64
#define Hn  256
#define On  128

// Partitioning: 16 batch groups x 8 column groups = 128 CTAs (all co-resident on 148 SMs)
#define RGRP 16
#define CGRP 8
#define BR   8      // batch rows per group
#define CN   32     // output columns per CTA
#define NTHREADS 256
#define K1   320    // D + H1  (x_t | h1_prev)
#define K2   512    // H1 + H2 (h1_t | h2_prev)
#define K1W  40     // K1 / 8 warps
#define K2W  64     // K2 / 8 warps

// Persistent device state (scratch; allocation-free per harness rules)
__device__ __align__(16) float g_H1[2][Bsz * Hn];
__device__ __align__(16) float g_H2[2][Bsz * Hn];
__device__ int g_f1[RGRP];
__device__ int g_f2[RGRP];

// ---------------------------------------------------------------------------
// Reset kernel: runs before the main kernel on every launch (graph-replay safe).
// Zeroes the monotonic flags and the t=0 hidden states.
// ---------------------------------------------------------------------------
__global__ void rnn_reset_kernel() {
    int idx = blockIdx.x * blockDim.x + threadIdx.x;
    if (idx < RGRP) { g_f1[idx] = 0; g_f2[idx] = 0; }
    const int n = Bsz * Hn;
    for (int i = idx; i < n; i += gridDim.x * blockDim.x) {
        g_H1[0][i] = 0.0f;
        g_H2[0][i] = 0.0f;
    }
}

// ---------------------------------------------------------------------------
// Persistent scan kernel.
// CTA (r, c): batch rows [r*8, r*8+8), output cols [c*32, c*32+32).
// 8 warps; warp w owns K-slice w of both layers; weights live in registers.
// ---------------------------------------------------------------------------
__global__ __launch_bounds__(NTHREADS, 1)
void rnn_scan_kernel(const float* __restrict__ x,
                     const float* __restrict__ Wx1, const float* __restrict__ Wh1,
                     const float* __restrict__ b1,
                     const float* __restrict__ Wx2, const float* __restrict__ Wh2,
                     const float* __restrict__ b2,
                     const float* __restrict__ Wd,  const float* __restrict__ bd,
                     float* __restrict__ out)
{
    __shared__ __align__(16) float sA1[BR][K1 + 8];   // [x_t | h1_prev] rows (pitch 328)
    __shared__ __align__(16) float sA2[BR][K2 + 8];   // [h1_t | h2_prev] rows (pitch 520)
    __shared__ __align__(16) float sRed[8][BR][CN];   // cross-warp K-slice partials

    const int cta = blockIdx.x;
    const int r   = cta / CGRP;
    const int c   = cta % CGRP;
    const int rb0 = r * BR;
    const int tid = threadIdx.x;
    const int w   = tid >> 5;     // warp id = K-slice (GEMM) / row (reduction)
    const int j   = tid & 31;     // lane = column within CN
    const int jg  = c * CN + j;   // global output column

    // ---- Load this thread's weight slices into registers (persist all steps) ----
    float wA1[K1W];
#pragma unroll
    for (int kk = 0; kk < K1W; kk++) {
        int kg = w * K1W + kk;
        wA1[kk] = (kg < Dn) ? __ldg(Wx1 + kg * Hn + jg)
                            : __ldg(Wh1 + (kg - Dn) * Hn + jg);
    }
    float wA2[K2W];
#pragma unroll
    for (int kk = 0; kk < K2W; kk++) {
        int kg = w * K2W + kk;
        wA2[kk] = (kg < Hn) ? __ldg(Wx2 + kg * Hn + jg)
                            : __ldg(Wh2 + (kg - Hn) * Hn + jg);
    }
    const float bias1 = __ldg(b1 + jg);
    const float bias2 = __ldg(b2 + jg);

    volatile int* vf1 = (volatile int*)&g_f1[r];
    volatile int* vf2 = (volatile int*)&g_f2[r];

    for (int t = 1; t <= Tn; t++) {
        const int pPrev = (t - 1) & 1;
        const int pCur  = t & 1;

        // ---- stage x_t rows (independent of any flag) ----
        if (tid < 128) {
            int row = tid >> 4, c4 = tid & 15;
            float4 v = __ldg((const float4*)(x + ((size_t)(rb0 + row) * Tn + (t - 1)) * Dn + c4 * 4));
            *(float4*)&sA1[row][c4 * 4] = v;
        }

        // ---- wait for h1_{t-1} complete across group, stage it ----
        if (tid == 0) {
            const int tgt = CGRP * (t - 1);
            while (*vf1 < tgt) __nanosleep(32);
        }
        __syncthreads();
        {
            const float* src = g_H1[pPrev];
#pragma unroll
            for (int i = 0; i < 2; i++) {
                int e = tid + i * NTHREADS;       // 0..511
                int row = e >> 6, c4 = e & 63;
                float4 v = __ldcg((const float4*)(src + (rb0 + row) * Hn + c4 * 4));
                *(float4*)&sA1[row][Dn + c4 * 4] = v;
            }
        }
        __syncthreads();

        // ---- layer-1 partial GEMM: K-slice w, 8 rows x 1 col per thread ----
        float acc[BR];
#pragma unroll
        for (int b_ = 0; b_ < BR; b_++) acc[b_] = 0.0f;
        {
            const int kbase = w * K1W;
#pragma unroll
            for (int kc = 0; kc < K1W / 4; kc++) {
                const int k = kbase + kc * 4;
                const float w0 = wA1[kc * 4 + 0], w1 = wA1[kc * 4 + 1];
                const float w2_ = wA1[kc * 4 + 2], w3 = wA1[kc * 4 + 3];
#pragma unroll
                for (int b_ = 0; b_ < BR; b_++) {
                    float4 a = *(const float4*)&sA1[b_][k];   // broadcast LDS.128
                    acc[b_] = fmaf(a.x, w0, acc[b_]);
                    acc[b_] = fmaf(a.y, w1, acc[b_]);
                    acc[b_] = fmaf(a.z, w2_, acc[b_]);
                    acc[b_] = fmaf(a.w, w3, acc[b_]);
                }
            }
        }
#pragma unroll
        for (int b_ = 0; b_ < BR; b_++) sRed[w][b_][j] = acc[b_];
        __syncthreads();
        {
            const int rb_ = w;                    // reduction: warp = row
            float v = bias1;
#pragma unroll
            for (int w2 = 0; w2 < 8; w2++) v += sRed[w2][rb_][j];
            v = tanhf(v);
            __stcg(&g_H1[pCur][(rb0 + rb_) * Hn + jg], v);
        }
        __threadfence();
        __syncthreads();
        if (tid == 0) atomicAdd(&g_f1[r], 1);

        // ---- wait for full h1_t and h2_{t-1}, stage both ----
        if (tid == 0) {
            const int tgt1 = CGRP * t;
            const int tgt2 = CGRP * (t - 1);
            while (*vf1 < tgt1) __nanosleep(32);
            while (*vf2 < tgt2) __nanosleep(32);
        }
        __syncthreads();
        {
            const float* s1 = g_H1[pCur];
            const float* s2 = g_H2[pPrev];
#pragma unroll
            for (int i = 0; i < 2; i++) {
                int e = tid + i * NTHREADS;
                int row = e >> 6, c4 = e & 63;
                float4 v1 = __ldcg((const float4*)(s1 + (rb0 + row) * Hn + c4 * 4));
                *(float4*)&sA2[row][c4 * 4] = v1;
                float4 v2 = __ldcg((const float4*)(s2 + (rb0 + row) * Hn + c4 * 4));
                *(float4*)&sA2[row][Hn + c4 * 4] = v2;
            }
        }
        __syncthreads();

        // ---- layer-2 partial GEMM ----
#pragma unroll
        for (int b_ = 0; b_ < BR; b_++) acc[b_] = 0.0f;
        {
            const int kbase = w * K2W;
#pragma unroll
            for (int kc = 0; kc < K2W / 4; kc++) {
                const int k = kbase + kc * 4;
                const float w0 = wA2[kc * 4 + 0], w1 = wA2[kc * 4 + 1];
                const float w2_ = wA2[kc * 4 + 2], w3 = wA2[kc * 4 + 3];
#pragma unroll
                for (int b_ = 0; b_ < BR; b_++) {
                    float4 a = *(const float4*)&sA2[b_][k];
                    acc[b_] = fmaf(a.x, w0, acc[b_]);
                    acc[b_] = fmaf(a.y, w1, acc[b_]);
                    acc[b_] = fmaf(a.z, w2_, acc[b_]);
                    acc[b_] = fmaf(a.w, w3, acc[b_]);
                }
            }
        }
#pragma unroll
        for (int b_ = 0; b_ < BR; b_++) sRed[w][b_][j] = acc[b_];
        __syncthreads();
        {
            const int rb_ = w;
            float v = bias2;
#pragma unroll
            for (int w2 = 0; w2 < 8; w2++) v += sRed[w2][rb_][j];
            v = tanhf(v);
            __stcg(&g_H2[pCur][(rb0 + rb_) * Hn + jg], v);
        }
        __threadfence();
        __syncthreads();
        if (tid == 0) atomicAdd(&g_f2[r], 1);
    }

    // ------------------- Epilogue: dense + softmax (c==0 CTAs) -------------------
    if (c != 0) return;

    if (tid == 0) {
        const int tgt = CGRP * Tn;
        while (*vf2 < tgt) __nanosleep(32);
    }
    __syncthreads();
    {
        const float* s2 = g_H2[Tn & 1];   // Tn even -> buffer 0
#pragma unroll
        for (int i = 0; i < 2; i++) {
            int e = tid + i * NTHREADS;
            int row = e >> 6, c4 = e & 63;
            float4 v = __ldcg((const float4*)(s2 + (rb0 + row) * Hn + c4 * 4));
            *(float4*)&sA2[row][c4 * 4] = v;
        }
    }
    __syncthreads();
    {
        const int b_ = w;                 // warp = batch row
        float l0 = __ldg(bd + j);
        float l1 = __ldg(bd + j + 32);
        float l2_ = __ldg(bd + j + 64);
        float l3 = __ldg(bd + j + 96);
#pragma unroll 4
        for (int k = 0; k < Hn; k++) {
            const float hv = sA2[b_][k];
            const float* wr = Wd + k * On;
            l0  = fmaf(hv, __ldg(wr + j),      l0);
            l1  = fmaf(hv, __ldg(wr + j + 32), l1);
            l2_ = fmaf(hv, __ldg(wr + j + 64), l2_);
            l3  = fmaf(hv, __ldg(wr + j + 96), l3);
        }
        // softmax across the 128 logits held by this warp (4 per lane)
        float m = fmaxf(fmaxf(l0, l1), fmaxf(l2_, l3));
#pragma unroll
        for (int off = 16; off; off >>= 1) m = fmaxf(m, __shfl_xor_sync(0xffffffffu, m, off));
        const float e0 = expf(l0 - m);
        const float e1 = expf(l1 - m);
        const float e2 = expf(l2_ - m);
        const float e3 = expf(l3 - m);
        float s = e0 + e1 + e2 + e3;
#pragma unroll
        for (int off = 16; off; off >>= 1) s += __shfl_xor_sync(0xffffffffu, s, off);
        const float inv = 1.0f / s;
        float* o = out + (rb0 + b_) * On;
        o[j]      = e0 * inv;
        o[j + 32] = e1 * inv;
        o[j + 64] = e2 * inv;
        o[j + 96] = e3 * inv;
    }
}

// ---------------------------------------------------------------------------
// Harness entry point (graph-capturable: two plain launches, no syncs/allocs)
// ---------------------------------------------------------------------------
extern "C" void kernel_launch(void* const* d_in, const int* in_sizes, int n_in,
                              void* d_out, int out_size) {
    (void)in_sizes; (void)n_in; (void)out_size;
    const float* x   = (const float*)d_in[0];
    const float* Wx1 = (const float*)d_in[1];
    const float* Wh1 = (const float*)d_in[2];
    const float* b1  = (const float*)d_in[3];
    const float* Wx2 = (const float*)d_in[4];
    const float* Wh2 = (const float*)d_in[5];
    const float* b2  = (const float*)d_in[6];
    const float* Wd  = (const float*)d_in[7];
    const float* bd  = (const float*)d_in[8];
    float* out = (float*)d_out;

    rnn_reset_kernel<<<64, 256>>>();
    rnn_scan_kernel<<<RGRP * CGRP, NTHREADS>>>(x, Wx1, Wh1, b1, Wx2, Wh2, b2, Wd, bd, out);
}

// round 7
// speedup vs baseline: 1.1828x; 1.1828x over previous
#include <cuda_runtime.h>
#include <cstdint>
#include <cstddef>

// Problem constants
#define Bsz 128
#define Tn  1024
#define Dn  64
#define Hn  256
#define On  128

// Partitioning: 16 batch groups x 8 column groups = 128 CTAs
#define RGRP 16
#define CGRP 8
#define BR   8      // batch rows per group
#define CN   32     // output columns per CTA
#define NTHREADS 256
#define K1W  40     // (D+H1)/8 warps
#define K2W  64     // (H1+H2)/8 warps
#define P1   72     // x buffer pitch (floats), 288B: 16B aligned
#define P2   520    // [h1|h2] buffer pitch (floats), 2080B: 16B aligned

// Persistent device state (allocation-free scratch)
__device__ __align__(16) float g_H1[2][Bsz * Hn];
__device__ __align__(16) float g_H2[2][Bsz * Hn];
__device__ int g_f1[RGRP];
__device__ int g_f2[RGRP];

// ---------------------------------------------------------------------------
__global__ void rnn_reset_kernel() {
    int idx = blockIdx.x * blockDim.x + threadIdx.x;
    if (idx < RGRP) { g_f1[idx] = 0; g_f2[idx] = 0; }
    const int n = Bsz * Hn;
    for (int i = idx; i < n; i += gridDim.x * blockDim.x) {
        g_H1[0][i] = 0.0f;
        g_H2[0][i] = 0.0f;
    }
}

// ---------------------------------------------------------------------------
// Packed fp32x2 FMA: (d.lo,d.hi) = (a.lo*b.lo+c.lo, a.hi*b.hi+c.hi)
__device__ __forceinline__ void ffma2(unsigned long long& acc,
                                      unsigned long long a,
                                      unsigned long long w) {
    asm("fma.rn.f32x2 %0, %1, %2, %0;" : "+l"(acc) : "l"(a), "l"(w));
}
__device__ __forceinline__ int ld_acq(const int* p) {
    int v;
    asm volatile("ld.acquire.gpu.global.s32 %0, [%1];" : "=r"(v) : "l"(p));
    return v;
}
__device__ __forceinline__ void red_rel(int* p) {
    asm volatile("red.release.gpu.global.add.s32 [%0], 1;" :: "l"(p) : "memory");
}

// ---------------------------------------------------------------------------
__global__ __launch_bounds__(NTHREADS, 1)
void rnn_scan_kernel(const float* __restrict__ x,
                     const float* __restrict__ Wx1, const float* __restrict__ Wh1,
                     const float* __restrict__ b1,
                     const float* __restrict__ Wx2, const float* __restrict__ Wh2,
                     const float* __restrict__ b2,
                     const float* __restrict__ Wd,  const float* __restrict__ bd,
                     float* __restrict__ out)
{
    __shared__ __align__(16) float sA1[BR][P1];          // x_t        (2.3 KB)
    __shared__ __align__(16) float sA2[2][BR][P2];       // [h1 | h2]  (33.3 KB)
    __shared__ __align__(16) float sRed[8][BR][CN];      // partials   (8 KB)

    const int cta = blockIdx.x;
    const int r   = cta / CGRP;
    const int c   = cta % CGRP;
    const int rb0 = r * BR;
    const int tid = threadIdx.x;
    const int w   = tid >> 5;
    const int j   = tid & 31;
    const int jg  = c * CN + j;

    // ---- weights, packed as consecutive-k f32 pairs (lo = even k) ----
    unsigned long long wq1[K1W / 2];
#pragma unroll
    for (int i = 0; i < K1W / 2; i++) {
        int k0 = w * K1W + 2 * i, k1 = k0 + 1;
        float f0 = (k0 < Dn) ? __ldg(Wx1 + k0 * Hn + jg) : __ldg(Wh1 + (k0 - Dn) * Hn + jg);
        float f1_ = (k1 < Dn) ? __ldg(Wx1 + k1 * Hn + jg) : __ldg(Wh1 + (k1 - Dn) * Hn + jg);
        wq1[i] = ((unsigned long long)__float_as_uint(f1_) << 32) | __float_as_uint(f0);
    }
    unsigned long long wq2[K2W / 2];
#pragma unroll
    for (int i = 0; i < K2W / 2; i++) {
        int k0 = w * K2W + 2 * i, k1 = k0 + 1;
        float f0 = (k0 < Hn) ? __ldg(Wx2 + k0 * Hn + jg) : __ldg(Wh2 + (k0 - Hn) * Hn + jg);
        float f1_ = (k1 < Hn) ? __ldg(Wx2 + k1 * Hn + jg) : __ldg(Wh2 + (k1 - Hn) * Hn + jg);
        wq2[i] = ((unsigned long long)__float_as_uint(f1_) << 32) | __float_as_uint(f0);
    }
    const float bias1 = __ldg(b1 + jg);
    const float bias2 = __ldg(b2 + jg);

    // zero smem h-buffers (h1_0 = 0 read at t=1)
    for (int i = tid; i < 2 * BR * P2; i += NTHREADS) ((float*)sA2)[i] = 0.0f;
    __syncthreads();

    int* f1p = &g_f1[r];
    int* f2p = &g_f2[r];

    const int e0r = tid >> 6, e0c = tid & 63;
    const int e1r = (tid + NTHREADS) >> 6, e1c = (tid + NTHREADS) & 63;

    for (int t = 1; t <= Tn; t++) {
        const int pPrev = (t - 1) & 1;
        const int pCur  = t & 1;

        // ---- stage x_t ----
        if (tid < 128) {
            int row = tid >> 4, c4 = tid & 15;
            float4 v = __ldg((const float4*)(x + ((size_t)(rb0 + row) * Tn + (t - 1)) * Dn + c4 * 4));
            *(float4*)&sA1[row][c4 * 4] = v;
        }
        // ---- h2_{t-1} availability (ample slack; overlaps layer 1) ----
        if (tid == 0) {
            const int tgt = CGRP * (t - 1);
            while (ld_acq(f2p) < tgt) {}
        }
        __syncthreads();                                            // bar1
        float4 h2a = __ldcg((const float4*)(g_H2[pPrev] + (rb0 + e0r) * Hn + e0c * 4));
        float4 h2b = __ldcg((const float4*)(g_H2[pPrev] + (rb0 + e1r) * Hn + e1c * 4));

        // ---- layer 1 GEMM (f32x2, even/odd-k split accumulators) ----
        unsigned long long acc[BR];
#pragma unroll
        for (int b_ = 0; b_ < BR; b_++) acc[b_] = 0ull;
        {
            const int kbase = w * K1W;
#pragma unroll
            for (int kc = 0; kc < K1W / 4; kc++) {
                const int k = kbase + kc * 4;
                const float* src; int str;
                if (k < Dn) { src = &sA1[0][k];               str = P1; }
                else        { src = &sA2[pPrev][0][k - Dn];   str = P2; }
                const unsigned long long w01 = wq1[2 * kc], w23 = wq1[2 * kc + 1];
#pragma unroll
                for (int b_ = 0; b_ < BR; b_++) {
                    ulonglong2 a = *(const ulonglong2*)src;   // broadcast LDS.128
                    ffma2(acc[b_], a.x, w01);
                    ffma2(acc[b_], a.y, w23);
                    src += str;
                }
            }
        }
        // park prefetched h2 into this step's layer-2 buffer
        *(float4*)&sA2[pCur][e0r][Hn + e0c * 4] = h2a;
        *(float4*)&sA2[pCur][e1r][Hn + e1c * 4] = h2b;
#pragma unroll
        for (int b_ = 0; b_ < BR; b_++) {
            float2 f = *(float2*)&acc[b_];
            sRed[w][b_][j] = f.x + f.y;
        }
        __syncthreads();                                            // bar2
        {
            float v = bias1;
#pragma unroll
            for (int w2 = 0; w2 < 8; w2++) v += sRed[w2][w][j];
            v = tanhf(v);
            __stcg(&g_H1[pCur][(rb0 + w) * Hn + jg], v);
        }
        __syncthreads();                                            // bar3
        if (tid == 0) {
            red_rel(f1p);                       // publish our h1 slice
            const int tgt = CGRP * t;
            while (ld_acq(f1p) < tgt) {}        // the one binding wait
        }
        __syncthreads();                                            // bar4
        // ---- stage full h1_t ----
#pragma unroll
        for (int i = 0; i < 2; i++) {
            int e = tid + i * NTHREADS;
            int row = e >> 6, c4 = e & 63;
            float4 v = __ldcg((const float4*)(g_H1[pCur] + (rb0 + row) * Hn + c4 * 4));
            *(float4*)&sA2[pCur][row][c4 * 4] = v;
        }
        __syncthreads();                                            // bar5

        // ---- layer 2 GEMM ----
#pragma unroll
        for (int b_ = 0; b_ < BR; b_++) acc[b_] = 0ull;
        {
            const int kbase = w * K2W;
#pragma unroll
            for (int kc = 0; kc < K2W / 4; kc++) {
                const float* src = &sA2[pCur][0][kbase + kc * 4];
                const unsigned long long w01 = wq2[2 * kc], w23 = wq2[2 * kc + 1];
#pragma unroll
                for (int b_ = 0; b_ < BR; b_++) {
                    ulonglong2 a = *(const ulonglong2*)src;
                    ffma2(acc[b_], a.x, w01);
                    ffma2(acc[b_], a.y, w23);
                    src += P2;
                }
            }
        }
#pragma unroll
        for (int b_ = 0; b_ < BR; b_++) {
            float2 f = *(float2*)&acc[b_];
            sRed[w][b_][j] = f.x + f.y;
        }
        __syncthreads();                                            // bar6
        {
            float v = bias2;
#pragma unroll
            for (int w2 = 0; w2 < 8; w2++) v += sRed[w2][w][j];
            v = tanhf(v);
            __stcg(&g_H2[pCur][(rb0 + w) * Hn + jg], v);
        }
        __syncthreads();                                            // bar7
        if (tid == 0) red_rel(f2p);
    }

    // ------------------- Epilogue: dense + softmax (c==0 CTAs) -------------------
    if (c != 0) return;

    if (tid == 0) {
        const int tgt = CGRP * Tn;
        while (ld_acq(f2p) < tgt) {}
    }
    __syncthreads();
#pragma unroll
    for (int i = 0; i < 2; i++) {
        int e = tid + i * NTHREADS;
        int row = e >> 6, c4 = e & 63;
        float4 v = __ldcg((const float4*)(g_H2[0] + (rb0 + row) * Hn + c4 * 4)); // Tn even
        *(float4*)&sA2[0][row][c4 * 4] = v;
    }
    __syncthreads();
    {
        const int b_ = w;                 // warp = batch row
        float l0 = __ldg(bd + j);
        float l1 = __ldg(bd + j + 32);
        float l2_ = __ldg(bd + j + 64);
        float l3 = __ldg(bd + j + 96);
#pragma unroll 4
        for (int k = 0; k < Hn; k++) {
            const float hv = sA2[0][b_][k];
            const float* wr = Wd + k * On;
            l0  = fmaf(hv, __ldg(wr + j),      l0);
            l1  = fmaf(hv, __ldg(wr + j + 32), l1);
            l2_ = fmaf(hv, __ldg(wr + j + 64), l2_);
            l3  = fmaf(hv, __ldg(wr + j + 96), l3);
        }
        float m = fmaxf(fmaxf(l0, l1), fmaxf(l2_, l3));
#pragma unroll
        for (int off = 16; off; off >>= 1) m = fmaxf(m, __shfl_xor_sync(0xffffffffu, m, off));
        const float e0 = expf(l0 - m);
        const float e1 = expf(l1 - m);
        const float e2 = expf(l2_ - m);
        const float e3 = expf(l3 - m);
        float s = e0 + e1 + e2 + e3;
#pragma unroll
        for (int off = 16; off; off >>= 1) s += __shfl_xor_sync(0xffffffffu, s, off);
        const float inv = 1.0f / s;
        float* o = out + (rb0 + b_) * On;
        o[j]      = e0 * inv;
        o[j + 32] = e1 * inv;
        o[j + 64] = e2 * inv;
        o[j + 96] = e3 * inv;
    }
}

// ---------------------------------------------------------------------------
extern "C" void kernel_launch(void* const* d_in, const int* in_sizes, int n_in,
                              void* d_out, int out_size) {
    (void)in_sizes; (void)n_in; (void)out_size;
    const float* x   = (const float*)d_in[0];
    const float* Wx1 = (const float*)d_in[1];
    const float* Wh1 = (const float*)d_in[2];
    const float* b1  = (const float*)d_in[3];
    const float* Wx2 = (const float*)d_in[4];
    const float* Wh2 = (const float*)d_in[5];
    const float* b2  = (const float*)d_in[6];
    const float* Wd  = (const float*)d_in[7];
    const float* bd  = (const float*)d_in[8];
    float* out = (float*)d_out;

    rnn_reset_kernel<<<64, 256>>>();
    rnn_scan_kernel<<<RGRP * CGRP, NTHREADS>>>(x, Wx1, Wh1, b1, Wx2, Wh2, b2, Wd, bd, out);
}